// round 3
// baseline (speedup 1.0000x reference)
#include <cuda_runtime.h>

// ---------------------------------------------------------------------------
// out[i, j] = f(j-1) - f(j)   where  f(j) = relu(1 - relu(x_full[j+1] - x) /
//                                              (x_full[j+1] - x_full[j] + 1e-9))
// with sentinels f(-1) = 1, f(n_full-1) = 0.  f(j) is exactly 1 left of the
// interval containing x and exactly 0 right of it (up to the eps window), so
// out is exactly 0 outside a <=8-column window around x's interval.
// Strategy: grid-stride float4 zero-fill (HBM write roofline), then a tiny
// scatter kernel writing the exact reference values in the window.
// ---------------------------------------------------------------------------

__global__ void zero_kernel(float4* __restrict__ out4, int n4,
                            float* __restrict__ out, int rem) {
    int stride = gridDim.x * blockDim.x;
    const float4 z = make_float4(0.f, 0.f, 0.f, 0.f);
    for (int i = blockIdx.x * blockDim.x + threadIdx.x; i < n4; i += stride)
        out4[i] = z;
    if (blockIdx.x == 0 && threadIdx.x == 0) {
        for (int r = 0; r < rem; ++r) out[4 * n4 + r] = 0.f;
    }
}

__device__ __forceinline__ float evalf(const float* __restrict__ xf,
                                       int j, int n_full, float x) {
    if (j < 0) return 1.0f;
    if (j >= n_full - 1) return 0.0f;
    float xa = __ldg(xf + j);
    float xb = __ldg(xf + j + 1);
    float t  = fmaxf(0.f, xb - x);
    return fmaxf(0.f, 1.0f - t / (xb - xa + 1e-9f));
}

__global__ void scatter_kernel(const float* __restrict__ x_eval,
                               const float* __restrict__ x_full,
                               float* __restrict__ out,
                               int n_points, int n_full) {
    int i = blockIdx.x * blockDim.x + threadIdx.x;
    if (i >= n_points) return;
    float x = x_eval[i];

    // upper_bound: lo = count of knots <= x
    int lo = 0, hi = n_full;
    while (lo < hi) {
        int mid = (lo + hi) >> 1;
        if (__ldg(x_full + mid) <= x) lo = mid + 1;
        else hi = mid;
    }
    int k = lo - 1;
    if (k < 0) k = 0;
    int kmax = n_full - 2;
    if (k > kmax) k = kmax;

    int n_cols = n_full;
    int j0 = (k - 2 < 0) ? 0 : (k - 2);
    int j1 = (k + 5 > n_cols - 1) ? (n_cols - 1) : (k + 5);

    int base = i * n_cols;
    float fprev = evalf(x_full, j0 - 1, n_full, x);
    #pragma unroll 1
    for (int j = j0; j <= j1; ++j) {
        float fj = evalf(x_full, j, n_full, x);
        out[base + j] = fprev - fj;
        fprev = fj;
    }
}

extern "C" void kernel_launch(void* const* d_in, const int* in_sizes, int n_in,
                              void* d_out, int out_size) {
    const float* x_eval = (const float*)d_in[0];  // (n_points, 1) float32
    const float* x_full = (const float*)d_in[1];  // (n_full,)    float32, sorted
    float* out = (float*)d_out;                   // (n_points, n_full) float32

    int n_points = in_sizes[0];
    int n_full   = in_sizes[1];

    // 1) zero-fill: persistent-ish grid-stride, 16 blocks/SM keeps warps
    //    resident so STG.128 issues back-to-back (fixes CTA-dispatch idle).
    int n4  = out_size >> 2;
    int rem = out_size & 3;
    int zb  = 148 * 16;                // 2368 blocks of 256
    zero_kernel<<<zb, 256>>>((float4*)out, n4, out, rem);

    // 2) exact values in the <=8-column window per row (x_full stays in L2)
    scatter_kernel<<<(n_points + 255) / 256, 256>>>(x_eval, x_full, out,
                                                    n_points, n_full);
}

// round 4
// speedup vs baseline: 1.1144x; 1.1144x over previous
#include <cuda_runtime.h>

// ---------------------------------------------------------------------------
// out[i, j] = f(j-1) - f(j),  f(j) = relu(1 - relu(x_full[j+1] - x) /
//                                         (x_full[j+1] - x_full[j] + 1e-9))
// sentinels f(-1)=1, f(n_full-1)=0.  out == 0 outside a <=8-column window
// around x's interval, so: roofline zero-fill + tiny exact scatter.
// ---------------------------------------------------------------------------

__global__ void zero_kernel(float4* __restrict__ out4, int n4,
                            float* __restrict__ out, int rem) {
    int i = blockIdx.x * blockDim.x + threadIdx.x;
    if (i < n4) {
        __stcs(out4 + i, make_float4(0.f, 0.f, 0.f, 0.f));  // streaming store
    }
    if (i == 0) {
        for (int r = 0; r < rem; ++r) out[4 * n4 + r] = 0.f;
    }
}

__device__ __forceinline__ float evalf_s(const float* __restrict__ sxf,
                                         int j, int n_full, float x) {
    if (j < 0) return 1.0f;
    if (j >= n_full - 1) return 0.0f;
    float xa = sxf[j];
    float xb = sxf[j + 1];
    float t  = fmaxf(0.f, xb - x);
    return fmaxf(0.f, 1.0f - t / (xb - xa + 1e-9f));
}

__global__ void scatter_kernel(const float* __restrict__ x_eval,
                               const float* __restrict__ x_full,
                               float* __restrict__ out,
                               int n_points, int n_full) {
    extern __shared__ float sxf[];   // n_full floats (8.2 KB for 2049)

    // cooperative, coalesced stage of the knot vector into smem
    for (int m = threadIdx.x; m < n_full; m += blockDim.x)
        sxf[m] = x_full[m];
    __syncthreads();

    int i = blockIdx.x * blockDim.x + threadIdx.x;
    if (i >= n_points) return;
    float x = x_eval[i];

    // upper_bound in smem: lo = count of knots <= x  (11 iters @ LDS latency)
    int lo = 0, hi = n_full;
    while (lo < hi) {
        int mid = (lo + hi) >> 1;
        if (sxf[mid] <= x) lo = mid + 1;
        else hi = mid;
    }
    int k = lo - 1;
    if (k < 0) k = 0;
    int kmax = n_full - 2;
    if (k > kmax) k = kmax;

    int n_cols = n_full;
    int j0 = (k - 2 < 0) ? 0 : (k - 2);
    int j1 = (k + 5 > n_cols - 1) ? (n_cols - 1) : (k + 5);

    int base = i * n_cols;
    float fprev = evalf_s(sxf, j0 - 1, n_full, x);
    #pragma unroll 1
    for (int j = j0; j <= j1; ++j) {
        float fj = evalf_s(sxf, j, n_full, x);
        out[base + j] = fprev - fj;
        fprev = fj;
    }
}

extern "C" void kernel_launch(void* const* d_in, const int* in_sizes, int n_in,
                              void* d_out, int out_size) {
    const float* x_eval = (const float*)d_in[0];  // (n_points, 1) float32
    const float* x_full = (const float*)d_in[1];  // (n_full,)    float32, sorted
    float* out = (float*)d_out;                   // (n_points, n_full) float32

    int n_points = in_sizes[0];
    int n_full   = in_sizes[1];

    // 1) zero-fill: one STG.128 per thread (measured best), streaming hint
    int n4  = out_size >> 2;
    int rem = out_size & 3;
    int zb  = (n4 + 255) / 256;
    if (zb < 1) zb = 1;
    zero_kernel<<<zb, 256>>>((float4*)out, n4, out, rem);

    // 2) exact values in the <=8-column window per row; knots in smem
    size_t smem = (size_t)n_full * sizeof(float);
    scatter_kernel<<<(n_points + 255) / 256, 256, smem>>>(x_eval, x_full, out,
                                                          n_points, n_full);
}